// round 14
// baseline (speedup 1.0000x reference)
#include <cuda_runtime.h>
#include <cuda_fp16.h>
#include <mma.h>
#include <cstdint>

using namespace nvcuda;

// Problem constants (DeformConvPack_39187281609181)
#define B_   4
#define C_   64
#define H_   128
#define W_   256
#define HW_  (H_ * W_)      // 32768
#define COUT 64
#define KK   9
#define HO   128
#define WO   256
#define NPIX (B_ * HO * WO) // 131072

#define TPX     128
#define THREADS 256

// smem layout (bytes)
#define LDA 72                             // A leading dim (144B rows)
#define LDB 72
#define A_BYTES (TPX * LDA * 2)            // 18432 per buffer
#define W_BUF   (C_ * LDB * 2)             // 9216 per buffer
#define SM_W    (2 * A_BYTES)              // 36864 ; A bufs at 0 and 18432
#define SM_TOTAL (SM_W + 2 * W_BUF)        // 55296
#define LDE 68                             // epilogue fp32 ldm (34816 <= 36864)

// Scratch (allocation-free)
__device__ __half g_xt[(size_t)B_ * HW_ * C_];   // x as NHWC fp16
__device__ __half g_wf[KK * C_ * COUT];          // weight fp16, [k][c][oc]

__device__ __forceinline__ uint32_t smem_u32(const void* p) {
    uint32_t a;
    asm("{ .reg .u64 t; cvta.to.shared.u64 t, %1; cvt.u32.u64 %0, t; }"
        : "=r"(a) : "l"(p));
    return a;
}
__device__ __forceinline__ void cp_async16(uint32_t dst, const void* src) {
    asm volatile("cp.async.ca.shared.global [%0], [%1], 16;"
                 :: "r"(dst), "l"(src) : "memory");
}

// ---------------------------------------------------------------------------
// Merged prep: blocks [0,8192) transpose x NCHW->NHWC fp16; rest convert W
__global__ void prep(const float* __restrict__ x, const float* __restrict__ w)
{
    if (blockIdx.x < 8192) {
        __shared__ float tile[32][33];
        const int bi  = blockIdx.x;
        const int b   = bi >> 11;
        const int c0  = ((bi >> 10) & 1) * 32;
        const int hw0 = (bi & 1023) * 32;
        const int tx  = threadIdx.x & 31;
        const int ty  = threadIdx.x >> 5;

        const float* xb = x + (size_t)b * C_ * HW_;
        #pragma unroll
        for (int i = 0; i < 32; i += 8)
            tile[ty + i][tx] = xb[(size_t)(c0 + ty + i) * HW_ + hw0 + tx];
        __syncthreads();

        __half* dst = g_xt + (size_t)b * HW_ * C_;
        const int c2 = threadIdx.x & 15;      // c pair
        const int rb = threadIdx.x >> 4;      // row base 0..15
        #pragma unroll
        for (int i = 0; i < 32; i += 16) {
            const int row = rb + i;
            __half2 v = __floats2half2_rn(tile[2 * c2][row], tile[2 * c2 + 1][row]);
            *(__half2*)(dst + (size_t)(hw0 + row) * C_ + c0 + 2 * c2) = v;
        }
    } else {
        // weight (Cout,Cin,3,3) -> fp16 [k][c][oc]
        const int t = (blockIdx.x - 8192) * 256 + threadIdx.x;   // 0..36863
        if (t < KK * C_ * COUT) {
            const int k  = t >> 12;
            const int c  = (t >> 6) & 63;
            const int oc = t & 63;
            g_wf[t] = __float2half(w[oc * (C_ * KK) + c * KK + k]);
        }
    }
}

// ---------------------------------------------------------------------------
// Warp-specialized main: warps 0-3 produce (gather + W stage), 4-7 consume (GEMM)
__global__ void __launch_bounds__(THREADS)
deform_main(const float* __restrict__ offset,
            const float* __restrict__ bias,
            float* __restrict__ out)
{
    extern __shared__ char sm[];
    const uint32_t smb = smem_u32(sm);

    const int tid = threadIdx.x;
    const int wid = tid >> 5;
    const int lid = tid & 31;
    const bool producer = (wid < 4);

    const int p0  = blockIdx.x * TPX;
    const int b   = p0 >> 15;
    const int ho  = (p0 & 32767) >> 8;
    const int wo0 = p0 & 255;

    // Consumer accumulators: consumer cw owns px rows [32cw, 32cw+32), all 64 oc
    wmma::fragment<wmma::accumulator, 16, 16, 16, float> acc[2][4];
    #pragma unroll
    for (int m = 0; m < 2; ++m)
        #pragma unroll
        for (int n = 0; n < 4; ++n) wmma::fill_fragment(acc[m][n], 0.0f);

    #pragma unroll 1
    for (int k = 0; k < KK; ++k) {
        const int buf = k & 1;

        if (producer) {
            __half* a_s = (__half*)(sm + buf * A_BYTES);

            // ---- stage W(k) -> buf (each producer warp: 16 c-rows) ----
            {
                const uint32_t wb = smb + SM_W + buf * W_BUF;
                const int c = wid * 16 + (lid >> 1);
                const __half* src = g_wf + k * (C_ * COUT) + c * COUT;
                #pragma unroll
                for (int j = 0; j < 4; ++j) {
                    const int seg = (lid & 1) * 4 + j;      // 0..7, 16B each
                    cp_async16(wb + c * 144 + seg * 16, src + seg * 8);
                }
                asm volatile("cp.async.commit_group;" ::: "memory");
            }

            // ---- bilinear meta: lane lid -> pixel 32*wid + lid ----
            float4 w4m; int4 i4m;
            {
                const int wo = wo0 + wid * 32 + lid;
                const size_t ob = (((size_t)b * (2 * KK) + 2 * k) * HO + ho) * WO + wo;
                const float dy = __ldg(offset + ob);
                const float dx = __ldg(offset + ob + (size_t)HO * WO);

                const int ky = k / 3, kx = k - 3 * ky;
                const float py = (float)(ho - 1 + ky) + dy;
                const float px = (float)(wo - 1 + kx) + dx;
                const float y0f = floorf(py), x0f = floorf(px);
                const float ly = py - y0f,  lx = px - x0f;
                const int y0 = (int)y0f, x0 = (int)x0f;
                const int y1 = y0 + 1,   x1 = x0 + 1;

                const float vy0 = (y0 >= 0 && y0 < H_) ? 1.0f : 0.0f;
                const float vy1 = (y1 >= 0 && y1 < H_) ? 1.0f : 0.0f;
                const float vx0 = (x0 >= 0 && x0 < W_) ? 1.0f : 0.0f;
                const float vx1 = (x1 >= 0 && x1 < W_) ? 1.0f : 0.0f;

                w4m.x = (1.0f - ly) * (1.0f - lx) * vy0 * vx0;
                w4m.y = (1.0f - ly) * lx          * vy0 * vx1;
                w4m.z = ly          * (1.0f - lx) * vy1 * vx0;
                w4m.w = ly          * lx          * vy1 * vx1;

                const int y0c = min(max(y0, 0), H_ - 1);
                const int y1c = min(max(y1, 0), H_ - 1);
                const int x0c = min(max(x0, 0), W_ - 1);
                const int x1c = min(max(x1, 0), W_ - 1);

                const int base = b * HW_;
                i4m.x = (base + y0c * W_ + x0c) * C_;
                i4m.y = (base + y0c * W_ + x1c) * C_;
                i4m.z = (base + y1c * W_ + x0c) * C_;
                i4m.w = (base + y1c * W_ + x1c) * C_;
            }

            // ---- gather the 32-px band: 8 iters x 4 px, lane = 8 channels ----
            #pragma unroll
            for (int it = 0; it < 8; ++it) {
                const int src = it * 4 + (lid >> 3);        // meta source lane
                const float wx = __shfl_sync(0xffffffffu, w4m.x, src);
                const float wy = __shfl_sync(0xffffffffu, w4m.y, src);
                const float wz = __shfl_sync(0xffffffffu, w4m.z, src);
                const float ww = __shfl_sync(0xffffffffu, w4m.w, src);
                const int   ia = __shfl_sync(0xffffffffu, i4m.x, src);
                const int   ib = __shfl_sync(0xffffffffu, i4m.y, src);
                const int   ic = __shfl_sync(0xffffffffu, i4m.z, src);
                const int   id = __shfl_sync(0xffffffffu, i4m.w, src);

                const __half2 wx2 = __float2half2_rn(wx);
                const __half2 wy2 = __float2half2_rn(wy);
                const __half2 wz2 = __float2half2_rn(wz);
                const __half2 ww2 = __float2half2_rn(ww);

                const int g8 = lid & 7;                     // 16B chunk in row
                const uint4 ua = __ldg((const uint4*)(g_xt + ia) + g8);
                const uint4 ub = __ldg((const uint4*)(g_xt + ib) + g8);
                const uint4 uc = __ldg((const uint4*)(g_xt + ic) + g8);
                const uint4 ud = __ldg((const uint4*)(g_xt + id) + g8);
                const __half2* ha = (const __half2*)&ua;
                const __half2* hb = (const __half2*)&ub;
                const __half2* hc = (const __half2*)&uc;
                const __half2* hd = (const __half2*)&ud;

                uint4 res;
                __half2* rv = (__half2*)&res;
                #pragma unroll
                for (int j = 0; j < 4; ++j) {
                    __half2 v = __hmul2(wx2, ha[j]);
                    v = __hfma2(wy2, hb[j], v);
                    v = __hfma2(wz2, hc[j], v);
                    v = __hfma2(ww2, hd[j], v);
                    rv[j] = v;
                }

                const int row = wid * 32 + it * 4 + (lid >> 3);
                *(uint4*)(a_s + row * LDA + g8 * 8) = res;
            }

            asm volatile("cp.async.wait_group 0;" ::: "memory");
        }

        __syncthreads();   // handoff: A(k)/W(k) ready; GEMM(k-1) done (WAR)

        if (!producer) {
            // ---- GEMM: consumer cw = wid-4 owns 32 px rows x 64 oc ----
            const int cw = wid - 4;
            const __half* w_k = (const __half*)(sm + SM_W + buf * W_BUF);
            const __half* ar  = (const __half*)(sm + buf * A_BYTES) + cw * 32 * LDA;
            #pragma unroll
            for (int kt = 0; kt < 4; ++kt) {
                wmma::fragment<wmma::matrix_a, 16, 16, 16, __half,
                               wmma::row_major> fa0, fa1;
                wmma::load_matrix_sync(fa0, ar + kt * 16, LDA);
                wmma::load_matrix_sync(fa1, ar + 16 * LDA + kt * 16, LDA);
                #pragma unroll
                for (int nt = 0; nt < 4; ++nt) {
                    wmma::fragment<wmma::matrix_b, 16, 16, 16, __half,
                                   wmma::row_major> fb;
                    wmma::load_matrix_sync(fb, w_k + kt * 16 * LDB + nt * 16, LDB);
                    wmma::mma_sync(acc[0][nt], fa0, fb, acc[0][nt]);
                    wmma::mma_sync(acc[1][nt], fa1, fb, acc[1][nt]);
                }
            }
        }
    }

    // ---- Epilogue: consumers dump acc -> fp32 smem; all threads STG ----
    __syncthreads();                       // producers idle, consumers done
    if (!producer) {
        float* smf = (float*)sm;           // reuse A region (34816 <= 36864)
        const int cw = wid - 4;
        #pragma unroll
        for (int m = 0; m < 2; ++m)
            #pragma unroll
            for (int nt = 0; nt < 4; ++nt)
                wmma::store_matrix_sync(smf + (cw * 32 + m * 16) * LDE + nt * 16,
                                        acc[m][nt], LDE, wmma::mem_row_major);
    }
    __syncthreads();
    {
        const float* smf = (const float*)sm;
        const int oc_g = tid >> 7;                    // 0/1
        const int pxe  = tid & 127;
        const size_t hw_out = (size_t)ho * WO + wo0 + pxe;
        #pragma unroll
        for (int o2 = 0; o2 < 32; ++o2) {
            const int oc = oc_g * 32 + o2;
            out[(size_t)(b * COUT + oc) * HW_ + hw_out] =
                smf[pxe * LDE + oc] + __ldg(bias + oc);
        }
    }
}

// ---------------------------------------------------------------------------
extern "C" void kernel_launch(void* const* d_in, const int* in_sizes, int n_in,
                              void* d_out, int out_size)
{
    const float* x      = (const float*)d_in[0];
    const float* offset = (const float*)d_in[1];
    const float* weight = (const float*)d_in[2];
    const float* bias   = (const float*)d_in[3];
    float* out = (float*)d_out;

    cudaFuncSetAttribute(deform_main,
                         cudaFuncAttributeMaxDynamicSharedMemorySize, SM_TOTAL);

    prep<<<8192 + (KK * C_ * COUT + 255) / 256, 256>>>(x, weight);
    deform_main<<<NPIX / TPX, THREADS, SM_TOTAL>>>(offset, bias, out);
}

// round 15
// speedup vs baseline: 1.5568x; 1.5568x over previous
#include <cuda_runtime.h>
#include <cuda_fp16.h>
#include <mma.h>
#include <cstdint>

using namespace nvcuda;

// Problem constants (DeformConvPack_39187281609181)
#define B_   4
#define C_   64
#define H_   128
#define W_   256
#define HW_  (H_ * W_)      // 32768
#define COUT 64
#define KK   9
#define HO   128
#define WO   256
#define NPIX (B_ * HO * WO) // 131072

#define TPX     128
#define THREADS 256

// smem layout (bytes)
#define LDA 72                             // A leading dim (144B rows)
#define LDB 72
#define A_BYTES (TPX * LDA * 2)            // 18432 per buffer
#define W_BUF   (C_ * LDB * 2)             // 9216 per buffer
#define SM_W    (2 * A_BYTES)              // 36864 ; A bufs at 0, 18432
#define SM_TOTAL (SM_W + 2 * W_BUF)        // 55296 -> 4 CTAs/SM
#define LDE 68                             // epilogue fp32 ldm (34816 <= 36864)

// Scratch (allocation-free)
__device__ __half g_xt[(size_t)B_ * HW_ * C_];   // x as NHWC fp16
__device__ __half g_wf[KK * C_ * COUT];          // weight fp16, [k][c][oc]

__device__ __forceinline__ uint32_t smem_u32(const void* p) {
    uint32_t a;
    asm("{ .reg .u64 t; cvta.to.shared.u64 t, %1; cvt.u32.u64 %0, t; }"
        : "=r"(a) : "l"(p));
    return a;
}
__device__ __forceinline__ void cp_async16(uint32_t dst, const void* src) {
    asm volatile("cp.async.ca.shared.global [%0], [%1], 16;"
                 :: "r"(dst), "l"(src) : "memory");
}

// ---------------------------------------------------------------------------
// Merged prep: blocks [0,8192) transpose x NCHW->NHWC fp16; rest convert W
__global__ void prep(const float* __restrict__ x, const float* __restrict__ w)
{
    if (blockIdx.x < 8192) {
        __shared__ float tile[32][33];
        const int bi  = blockIdx.x;
        const int b   = bi >> 11;
        const int c0  = ((bi >> 10) & 1) * 32;
        const int hw0 = (bi & 1023) * 32;
        const int tx  = threadIdx.x & 31;
        const int ty  = threadIdx.x >> 5;

        const float* xb = x + (size_t)b * C_ * HW_;
        #pragma unroll
        for (int i = 0; i < 32; i += 8)
            tile[ty + i][tx] = xb[(size_t)(c0 + ty + i) * HW_ + hw0 + tx];
        __syncthreads();

        __half* dst = g_xt + (size_t)b * HW_ * C_;
        const int c2 = threadIdx.x & 15;      // c pair
        const int rb = threadIdx.x >> 4;      // row base 0..15
        #pragma unroll
        for (int i = 0; i < 32; i += 16) {
            const int row = rb + i;
            __half2 v = __floats2half2_rn(tile[2 * c2][row], tile[2 * c2 + 1][row]);
            *(__half2*)(dst + (size_t)(hw0 + row) * C_ + c0 + 2 * c2) = v;
        }
    } else {
        // weight (Cout,Cin,3,3) -> fp16 [k][c][oc]
        const int t = (blockIdx.x - 8192) * 256 + threadIdx.x;   // 0..36863
        if (t < KK * C_ * COUT) {
            const int k  = t >> 12;
            const int c  = (t >> 6) & 63;
            const int oc = t & 63;
            g_wf[t] = __float2half(w[oc * (C_ * KK) + c * KK + k]);
        }
    }
}

// ---------------------------------------------------------------------------
__global__ void __launch_bounds__(THREADS, 4)
deform_main(const float* __restrict__ offset,
            const float* __restrict__ bias,
            float* __restrict__ out)
{
    extern __shared__ char sm[];
    const uint32_t smb = smem_u32(sm);

    const int tid = threadIdx.x;
    const int wid = tid >> 5;
    const int lid = tid & 31;

    const int p0  = blockIdx.x * TPX;
    const int b   = p0 >> 15;
    const int ho  = (p0 & 32767) >> 8;
    const int wo0 = p0 & 255;

    // GEMM tile: warp (mb = wid&3, nb = wid>>2) owns 32 px x 32 oc
    const int mb = (wid & 3) * 32;
    const int nb = (wid >> 2) * 32;

    wmma::fragment<wmma::accumulator, 16, 16, 16, float> acc[2][2];
    #pragma unroll
    for (int m = 0; m < 2; ++m)
        #pragma unroll
        for (int n = 0; n < 2; ++n) wmma::fill_fragment(acc[m][n], 0.0f);

    #pragma unroll 1
    for (int k = 0; k < KK; ++k) {
        const int buf = k & 1;
        __half* a_s = (__half*)(sm + buf * A_BYTES);

        // ---- stage W(k) -> buf via cp.async (warp: 8 c-rows of 128B) ----
        {
            const uint32_t wb = smb + SM_W + buf * W_BUF;
            const int c   = wid * 8 + (lid >> 2);
            const __half* src = g_wf + k * (C_ * COUT) + c * COUT;
            #pragma unroll
            for (int j = 0; j < 2; ++j) {
                const int seg = (lid & 3) * 2 + j;          // 0..7, 16B each
                cp_async16(wb + c * 144 + seg * 16, src + seg * 8);
            }
            asm volatile("cp.async.commit_group;" ::: "memory");
        }

        // ---- warp-local bilinear meta for pixel 16*wid + (lid&15) ----
        float4 w4m; int4 i4m;
        {
            const int pxl = lid & 15;
            const int wo  = wo0 + wid * 16 + pxl;
            const size_t ob = (((size_t)b * (2 * KK) + 2 * k) * HO + ho) * WO + wo;
            const float dy = __ldg(offset + ob);
            const float dx = __ldg(offset + ob + (size_t)HO * WO);

            const int ky = k / 3, kx = k - 3 * ky;
            const float py = (float)(ho - 1 + ky) + dy;
            const float px = (float)(wo - 1 + kx) + dx;
            const float y0f = floorf(py), x0f = floorf(px);
            const float ly = py - y0f,  lx = px - x0f;
            const int y0 = (int)y0f, x0 = (int)x0f;
            const int y1 = y0 + 1,   x1 = x0 + 1;

            const float vy0 = (y0 >= 0 && y0 < H_) ? 1.0f : 0.0f;
            const float vy1 = (y1 >= 0 && y1 < H_) ? 1.0f : 0.0f;
            const float vx0 = (x0 >= 0 && x0 < W_) ? 1.0f : 0.0f;
            const float vx1 = (x1 >= 0 && x1 < W_) ? 1.0f : 0.0f;

            w4m.x = (1.0f - ly) * (1.0f - lx) * vy0 * vx0;
            w4m.y = (1.0f - ly) * lx          * vy0 * vx1;
            w4m.z = ly          * (1.0f - lx) * vy1 * vx0;
            w4m.w = ly          * lx          * vy1 * vx1;

            const int y0c = min(max(y0, 0), H_ - 1);
            const int y1c = min(max(y1, 0), H_ - 1);
            const int x0c = min(max(x0, 0), W_ - 1);
            const int x1c = min(max(x1, 0), W_ - 1);

            const int base = b * HW_;
            i4m.x = (base + y0c * W_ + x0c) * C_;
            i4m.y = (base + y0c * W_ + x1c) * C_;
            i4m.z = (base + y1c * W_ + x0c) * C_;
            i4m.w = (base + y1c * W_ + x1c) * C_;
        }

        // ---- gather warp's 16 px: 4 iters x 4 px, lane = 8 channels ----
        #pragma unroll
        for (int it = 0; it < 4; ++it) {
            const int src = it * 4 + (lid >> 3);            // meta source lane
            const float wx = __shfl_sync(0xffffffffu, w4m.x, src);
            const float wy = __shfl_sync(0xffffffffu, w4m.y, src);
            const float wz = __shfl_sync(0xffffffffu, w4m.z, src);
            const float ww = __shfl_sync(0xffffffffu, w4m.w, src);
            const int   ia = __shfl_sync(0xffffffffu, i4m.x, src);
            const int   ib = __shfl_sync(0xffffffffu, i4m.y, src);
            const int   ic = __shfl_sync(0xffffffffu, i4m.z, src);
            const int   id = __shfl_sync(0xffffffffu, i4m.w, src);

            const __half2 wx2 = __float2half2_rn(wx);
            const __half2 wy2 = __float2half2_rn(wy);
            const __half2 wz2 = __float2half2_rn(wz);
            const __half2 ww2 = __float2half2_rn(ww);

            const int g8 = lid & 7;                         // 16B chunk in row
            const uint4 ua = __ldg((const uint4*)(g_xt + ia) + g8);
            const uint4 ub = __ldg((const uint4*)(g_xt + ib) + g8);
            const uint4 uc = __ldg((const uint4*)(g_xt + ic) + g8);
            const uint4 ud = __ldg((const uint4*)(g_xt + id) + g8);
            const __half2* ha = (const __half2*)&ua;
            const __half2* hb = (const __half2*)&ub;
            const __half2* hc = (const __half2*)&uc;
            const __half2* hd = (const __half2*)&ud;

            uint4 res;
            __half2* rv = (__half2*)&res;
            #pragma unroll
            for (int j = 0; j < 4; ++j) {
                __half2 v = __hmul2(wx2, ha[j]);
                v = __hfma2(wy2, hb[j], v);
                v = __hfma2(wz2, hc[j], v);
                v = __hfma2(ww2, hd[j], v);
                rv[j] = v;
            }

            const int row = wid * 16 + it * 4 + (lid >> 3);
            *(uint4*)(a_s + row * LDA + g8 * 8) = res;
        }

        asm volatile("cp.async.wait_group 0;" ::: "memory");
        __syncthreads();   // the ONE barrier per k (A/W double-buffered)

        // ---- GEMM: 2x2 tile -> 2 fa + 2 fb loads per kt, 4 mma ----
        {
            const __half* w_k  = (const __half*)(sm + SM_W + buf * W_BUF);
            const __half* ar   = a_s + mb * LDA;
            #pragma unroll
            for (int kt = 0; kt < 4; ++kt) {
                wmma::fragment<wmma::matrix_a, 16, 16, 16, __half,
                               wmma::row_major> fa0, fa1;
                wmma::load_matrix_sync(fa0, ar + kt * 16, LDA);
                wmma::load_matrix_sync(fa1, ar + 16 * LDA + kt * 16, LDA);
                wmma::fragment<wmma::matrix_b, 16, 16, 16, __half,
                               wmma::row_major> fb0, fb1;
                wmma::load_matrix_sync(fb0, w_k + kt * 16 * LDB + nb, LDB);
                wmma::load_matrix_sync(fb1, w_k + kt * 16 * LDB + nb + 16, LDB);
                wmma::mma_sync(acc[0][0], fa0, fb0, acc[0][0]);
                wmma::mma_sync(acc[0][1], fa0, fb1, acc[0][1]);
                wmma::mma_sync(acc[1][0], fa1, fb0, acc[1][0]);
                wmma::mma_sync(acc[1][1], fa1, fb1, acc[1][1]);
            }
        }
    }

    // ---- Epilogue: acc -> fp32 smem [128][LDE] -> transposed coalesced STG ----
    __syncthreads();                       // all warps done with A/W smem
    {
        float* smf = (float*)sm;           // reuse A region (34816 <= 36864)
        #pragma unroll
        for (int m = 0; m < 2; ++m)
            #pragma unroll
            for (int n = 0; n < 2; ++n)
                wmma::store_matrix_sync(smf + (mb + m * 16) * LDE + nb + n * 16,
                                        acc[m][n], LDE, wmma::mem_row_major);
    }
    __syncthreads();
    {
        const float* smf = (const float*)sm;
        const int oc_g = tid >> 7;                    // 0/1
        const int pxe  = tid & 127;
        const size_t hw_out = (size_t)ho * WO + wo0 + pxe;
        #pragma unroll
        for (int o2 = 0; o2 < 32; ++o2) {
            const int oc = oc_g * 32 + o2;
            out[(size_t)(b * COUT + oc) * HW_ + hw_out] =
                smf[pxe * LDE + oc] + __ldg(bias + oc);
        }
    }
}

// ---------------------------------------------------------------------------
extern "C" void kernel_launch(void* const* d_in, const int* in_sizes, int n_in,
                              void* d_out, int out_size)
{
    const float* x      = (const float*)d_in[0];
    const float* offset = (const float*)d_in[1];
    const float* weight = (const float*)d_in[2];
    const float* bias   = (const float*)d_in[3];
    float* out = (float*)d_out;

    cudaFuncSetAttribute(deform_main,
                         cudaFuncAttributeMaxDynamicSharedMemorySize, SM_TOTAL);

    prep<<<8192 + (KK * C_ * COUT + 255) / 256, 256>>>(x, weight);
    deform_main<<<NPIX / TPX, THREADS, SM_TOTAL>>>(offset, bias, out);
}

// round 16
// speedup vs baseline: 1.8562x; 1.1923x over previous
#include <cuda_runtime.h>
#include <cuda_fp16.h>
#include <mma.h>
#include <cstdint>

using namespace nvcuda;

// Problem constants (DeformConvPack_39187281609181)
#define B_   4
#define C_   64
#define H_   128
#define W_   256
#define HW_  (H_ * W_)      // 32768
#define COUT 64
#define KK   9
#define HO   128
#define WO   256
#define NPIX (B_ * HO * WO) // 131072

#define TPX     128
#define THREADS 256

// smem layout (bytes)
#define LDA 72                             // A leading dim (144B rows)
#define LDB 72
#define A_BYTES (TPX * LDA * 2)            // 18432 per buffer
#define W_BUF   (C_ * LDB * 2)             // 9216 per buffer
#define SM_W    (2 * A_BYTES)              // 36864 ; A bufs at 0, 18432
#define SM_TOTAL (SM_W + 2 * W_BUF)        // 55296 -> 3 CTAs/SM at <=84 regs
#define LDE 68                             // epilogue fp32 ldm (34816 <= 36864)

// Scratch (allocation-free)
__device__ __half g_xt[(size_t)B_ * HW_ * C_];   // x as NHWC fp16
__device__ __half g_wf[KK * C_ * COUT];          // weight fp16, [k][c][oc]

__device__ __forceinline__ uint32_t smem_u32(const void* p) {
    uint32_t a;
    asm("{ .reg .u64 t; cvta.to.shared.u64 t, %1; cvt.u32.u64 %0, t; }"
        : "=r"(a) : "l"(p));
    return a;
}
__device__ __forceinline__ void cp_async16(uint32_t dst, const void* src) {
    asm volatile("cp.async.ca.shared.global [%0], [%1], 16;"
                 :: "r"(dst), "l"(src) : "memory");
}

// ---------------------------------------------------------------------------
// Merged prep: blocks [0,8192) transpose x NCHW->NHWC fp16; rest convert W
__global__ void prep(const float* __restrict__ x, const float* __restrict__ w)
{
    if (blockIdx.x < 8192) {
        __shared__ float tile[32][33];
        const int bi  = blockIdx.x;
        const int b   = bi >> 11;
        const int c0  = ((bi >> 10) & 1) * 32;
        const int hw0 = (bi & 1023) * 32;
        const int tx  = threadIdx.x & 31;
        const int ty  = threadIdx.x >> 5;

        const float* xb = x + (size_t)b * C_ * HW_;
        #pragma unroll
        for (int i = 0; i < 32; i += 8)
            tile[ty + i][tx] = xb[(size_t)(c0 + ty + i) * HW_ + hw0 + tx];
        __syncthreads();

        __half* dst = g_xt + (size_t)b * HW_ * C_;
        const int c2 = threadIdx.x & 15;      // c pair
        const int rb = threadIdx.x >> 4;      // row base 0..15
        #pragma unroll
        for (int i = 0; i < 32; i += 16) {
            const int row = rb + i;
            __half2 v = __floats2half2_rn(tile[2 * c2][row], tile[2 * c2 + 1][row]);
            *(__half2*)(dst + (size_t)(hw0 + row) * C_ + c0 + 2 * c2) = v;
        }
    } else {
        // weight (Cout,Cin,3,3) -> fp16 [k][c][oc]
        const int t = (blockIdx.x - 8192) * 256 + threadIdx.x;   // 0..36863
        if (t < KK * C_ * COUT) {
            const int k  = t >> 12;
            const int c  = (t >> 6) & 63;
            const int oc = t & 63;
            g_wf[t] = __float2half(w[oc * (C_ * KK) + c * KK + k]);
        }
    }
}

// ---------------------------------------------------------------------------
__global__ void __launch_bounds__(THREADS, 3)
deform_main(const float* __restrict__ offset,
            const float* __restrict__ bias,
            float* __restrict__ out)
{
    extern __shared__ char sm[];
    const uint32_t smb = smem_u32(sm);

    const int tid = threadIdx.x;
    const int wid = tid >> 5;
    const int lid = tid & 31;

    const int p0  = blockIdx.x * TPX;
    const int b   = p0 >> 15;
    const int ho  = (p0 & 32767) >> 8;
    const int wo0 = p0 & 255;

    // GEMM tile: warp (mb = wid&3, nb = wid>>2) owns 32 px x 32 oc
    const int mb = (wid & 3) * 32;
    const int nb = (wid >> 2) * 32;

    wmma::fragment<wmma::accumulator, 16, 16, 16, float> acc[2][2];
    #pragma unroll
    for (int m = 0; m < 2; ++m)
        #pragma unroll
        for (int n = 0; n < 2; ++n) wmma::fill_fragment(acc[m][n], 0.0f);

    #pragma unroll 1
    for (int k = 0; k < KK; ++k) {
        const int buf = k & 1;
        __half* a_s = (__half*)(sm + buf * A_BYTES);

        // ---- stage W(k) -> buf via cp.async (warp: 8 c-rows of 128B) ----
        {
            const uint32_t wb = smb + SM_W + buf * W_BUF;
            const int c   = wid * 8 + (lid >> 2);
            const __half* src = g_wf + k * (C_ * COUT) + c * COUT;
            #pragma unroll
            for (int j = 0; j < 2; ++j) {
                const int seg = (lid & 3) * 2 + j;          // 0..7, 16B each
                cp_async16(wb + c * 144 + seg * 16, src + seg * 8);
            }
            asm volatile("cp.async.commit_group;" ::: "memory");
        }

        // ---- warp-local bilinear meta for pixel 16*wid + (lid&15) ----
        float4 w4m; int4 i4m;
        {
            const int pxl = lid & 15;
            const int wo  = wo0 + wid * 16 + pxl;
            const size_t ob = (((size_t)b * (2 * KK) + 2 * k) * HO + ho) * WO + wo;
            const float dy = __ldg(offset + ob);
            const float dx = __ldg(offset + ob + (size_t)HO * WO);

            const int ky = k / 3, kx = k - 3 * ky;
            const float py = (float)(ho - 1 + ky) + dy;
            const float px = (float)(wo - 1 + kx) + dx;
            const float y0f = floorf(py), x0f = floorf(px);
            const float ly = py - y0f,  lx = px - x0f;
            const int y0 = (int)y0f, x0 = (int)x0f;
            const int y1 = y0 + 1,   x1 = x0 + 1;

            const float vy0 = (y0 >= 0 && y0 < H_) ? 1.0f : 0.0f;
            const float vy1 = (y1 >= 0 && y1 < H_) ? 1.0f : 0.0f;
            const float vx0 = (x0 >= 0 && x0 < W_) ? 1.0f : 0.0f;
            const float vx1 = (x1 >= 0 && x1 < W_) ? 1.0f : 0.0f;

            w4m.x = (1.0f - ly) * (1.0f - lx) * vy0 * vx0;
            w4m.y = (1.0f - ly) * lx          * vy0 * vx1;
            w4m.z = ly          * (1.0f - lx) * vy1 * vx0;
            w4m.w = ly          * lx          * vy1 * vx1;

            const int y0c = min(max(y0, 0), H_ - 1);
            const int y1c = min(max(y1, 0), H_ - 1);
            const int x0c = min(max(x0, 0), W_ - 1);
            const int x1c = min(max(x1, 0), W_ - 1);

            const int base = b * HW_;
            i4m.x = (base + y0c * W_ + x0c) * C_;
            i4m.y = (base + y0c * W_ + x1c) * C_;
            i4m.z = (base + y1c * W_ + x0c) * C_;
            i4m.w = (base + y1c * W_ + x1c) * C_;
        }

        // ---- gather warp's 16 px: 4 iters x 4 px, lane = 8 channels ----
        #pragma unroll
        for (int it = 0; it < 4; ++it) {
            const int src = it * 4 + (lid >> 3);            // meta source lane
            const float wx = __shfl_sync(0xffffffffu, w4m.x, src);
            const float wy = __shfl_sync(0xffffffffu, w4m.y, src);
            const float wz = __shfl_sync(0xffffffffu, w4m.z, src);
            const float ww = __shfl_sync(0xffffffffu, w4m.w, src);
            const int   ia = __shfl_sync(0xffffffffu, i4m.x, src);
            const int   ib = __shfl_sync(0xffffffffu, i4m.y, src);
            const int   ic = __shfl_sync(0xffffffffu, i4m.z, src);
            const int   id = __shfl_sync(0xffffffffu, i4m.w, src);

            const __half2 wx2 = __float2half2_rn(wx);
            const __half2 wy2 = __float2half2_rn(wy);
            const __half2 wz2 = __float2half2_rn(wz);
            const __half2 ww2 = __float2half2_rn(ww);

            const int g8 = lid & 7;                         // 16B chunk in row
            const uint4 ua = __ldg((const uint4*)(g_xt + ia) + g8);
            const uint4 ub = __ldg((const uint4*)(g_xt + ib) + g8);
            const uint4 uc = __ldg((const uint4*)(g_xt + ic) + g8);
            const uint4 ud = __ldg((const uint4*)(g_xt + id) + g8);
            const __half2* ha = (const __half2*)&ua;
            const __half2* hb = (const __half2*)&ub;
            const __half2* hc = (const __half2*)&uc;
            const __half2* hd = (const __half2*)&ud;

            uint4 res;
            __half2* rv = (__half2*)&res;
            #pragma unroll
            for (int j = 0; j < 4; ++j) {
                __half2 v = __hmul2(wx2, ha[j]);
                v = __hfma2(wy2, hb[j], v);
                v = __hfma2(wz2, hc[j], v);
                v = __hfma2(ww2, hd[j], v);
                rv[j] = v;
            }

            const int row = wid * 16 + it * 4 + (lid >> 3);
            *(uint4*)(a_s + row * LDA + g8 * 8) = res;
        }

        asm volatile("cp.async.wait_group 0;" ::: "memory");
        __syncthreads();   // the ONE barrier per k (A/W double-buffered)

        // ---- GEMM: 2x2 tile -> 2 fa + 2 fb loads per kt, 4 mma ----
        {
            const __half* w_k  = (const __half*)(sm + SM_W + buf * W_BUF);
            const __half* ar   = a_s + mb * LDA;
            #pragma unroll
            for (int kt = 0; kt < 4; ++kt) {
                wmma::fragment<wmma::matrix_a, 16, 16, 16, __half,
                               wmma::row_major> fa0, fa1;
                wmma::load_matrix_sync(fa0, ar + kt * 16, LDA);
                wmma::load_matrix_sync(fa1, ar + 16 * LDA + kt * 16, LDA);
                wmma::fragment<wmma::matrix_b, 16, 16, 16, __half,
                               wmma::row_major> fb0, fb1;
                wmma::load_matrix_sync(fb0, w_k + kt * 16 * LDB + nb, LDB);
                wmma::load_matrix_sync(fb1, w_k + kt * 16 * LDB + nb + 16, LDB);
                wmma::mma_sync(acc[0][0], fa0, fb0, acc[0][0]);
                wmma::mma_sync(acc[0][1], fa0, fb1, acc[0][1]);
                wmma::mma_sync(acc[1][0], fa1, fb0, acc[1][0]);
                wmma::mma_sync(acc[1][1], fa1, fb1, acc[1][1]);
            }
        }
    }

    // ---- Epilogue: acc -> fp32 smem [128][LDE] -> transposed coalesced STG ----
    __syncthreads();                       // all warps done with A/W smem
    {
        float* smf = (float*)sm;           // reuse A region (34816 <= 36864)
        #pragma unroll
        for (int m = 0; m < 2; ++m)
            #pragma unroll
            for (int n = 0; n < 2; ++n)
                wmma::store_matrix_sync(smf + (mb + m * 16) * LDE + nb + n * 16,
                                        acc[m][n], LDE, wmma::mem_row_major);
    }
    __syncthreads();
    {
        const float* smf = (const float*)sm;
        const int oc_g = tid >> 7;                    // 0/1
        const int pxe  = tid & 127;
        const size_t hw_out = (size_t)ho * WO + wo0 + pxe;
        #pragma unroll
        for (int o2 = 0; o2 < 32; ++o2) {
            const int oc = oc_g * 32 + o2;
            out[(size_t)(b * COUT + oc) * HW_ + hw_out] =
                smf[pxe * LDE + oc] + __ldg(bias + oc);
        }
    }
}

// ---------------------------------------------------------------------------
extern "C" void kernel_launch(void* const* d_in, const int* in_sizes, int n_in,
                              void* d_out, int out_size)
{
    const float* x      = (const float*)d_in[0];
    const float* offset = (const float*)d_in[1];
    const float* weight = (const float*)d_in[2];
    const float* bias   = (const float*)d_in[3];
    float* out = (float*)d_out;

    cudaFuncSetAttribute(deform_main,
                         cudaFuncAttributeMaxDynamicSharedMemorySize, SM_TOTAL);

    prep<<<8192 + (KK * C_ * COUT + 255) / 256, 256>>>(x, weight);
    deform_main<<<NPIX / TPX, THREADS, SM_TOTAL>>>(offset, bias, out);
}

// round 17
// speedup vs baseline: 1.9396x; 1.0449x over previous
#include <cuda_runtime.h>
#include <cuda_fp16.h>
#include <mma.h>
#include <cstdint>

using namespace nvcuda;

// Problem constants (DeformConvPack_39187281609181)
#define B_   4
#define C_   64
#define H_   128
#define W_   256
#define HW_  (H_ * W_)      // 32768
#define COUT 64
#define KK   9
#define HO   128
#define WO   256
#define NPIX (B_ * HO * WO) // 131072

#define TPX     128
#define THREADS 256

// smem layout (bytes)
#define LDA 72                             // A leading dim (144B rows)
#define LDB 72
#define A_BYTES (TPX * LDA * 2)            // 18432 per buffer
#define W_BUF   (C_ * LDB * 2)             // 9216 per buffer
#define SM_W    (2 * A_BYTES)              // 36864 ; A bufs at 0, 18432
#define SM_TOTAL (SM_W + 2 * W_BUF)        // 55296 -> 3 CTAs/SM at ~80 regs
#define LDE 68                             // epilogue fp32 ldm (34816 <= 36864)

// Scratch (allocation-free)
__device__ __half g_xt[(size_t)B_ * HW_ * C_];   // x as NHWC fp16
__device__ __half g_wf[KK * C_ * COUT];          // weight fp16, [k][c][oc]

__device__ __forceinline__ uint32_t smem_u32(const void* p) {
    uint32_t a;
    asm("{ .reg .u64 t; cvta.to.shared.u64 t, %1; cvt.u32.u64 %0, t; }"
        : "=r"(a) : "l"(p));
    return a;
}
__device__ __forceinline__ void cp_async16(uint32_t dst, const void* src) {
    asm volatile("cp.async.ca.shared.global [%0], [%1], 16;"
                 :: "r"(dst), "l"(src) : "memory");
}

// ---------------------------------------------------------------------------
// Merged prep: blocks [0,4096) transpose x NCHW->NHWC fp16 (fully coalesced
// 128B-row stores); blocks [4096, 4096+144) convert W.
__global__ void prep(const float* __restrict__ x, const float* __restrict__ w)
{
    if (blockIdx.x < 4096) {
        __shared__ float tile[64][33];
        const int bi  = blockIdx.x;
        const int b   = bi >> 10;
        const int hw0 = (bi & 1023) * 32;
        const int tx  = threadIdx.x & 31;
        const int ty  = threadIdx.x >> 5;     // 0..7

        const float* xb = x + (size_t)b * C_ * HW_;
        #pragma unroll
        for (int i = 0; i < 64; i += 8)       // c rows
            tile[ty + i][tx] = xb[(size_t)(ty + i) * HW_ + hw0 + tx];
        __syncthreads();

        // write: thread -> pixel row r (0..31), channels c8*8..c8*8+7 (16B)
        __half* dst = g_xt + (size_t)b * HW_ * C_;
        const int r  = threadIdx.x >> 3;      // 0..31
        const int c8 = threadIdx.x & 7;       // 0..7
        uint4 pk;
        __half2* ph = (__half2*)&pk;
        #pragma unroll
        for (int j = 0; j < 4; ++j)
            ph[j] = __floats2half2_rn(tile[c8 * 8 + 2 * j][r],
                                      tile[c8 * 8 + 2 * j + 1][r]);
        *(uint4*)(dst + (size_t)(hw0 + r) * C_ + c8 * 8) = pk;
    } else {
        // weight (Cout,Cin,3,3) -> fp16 [k][c][oc]
        const int t = (blockIdx.x - 4096) * 256 + threadIdx.x;   // 0..36863
        if (t < KK * C_ * COUT) {
            const int k  = t >> 12;
            const int c  = (t >> 6) & 63;
            const int oc = t & 63;
            g_wf[t] = __float2half(w[oc * (C_ * KK) + c * KK + k]);
        }
    }
}

// ---------------------------------------------------------------------------
__global__ void __launch_bounds__(THREADS, 3)
deform_main(const float* __restrict__ offset,
            const float* __restrict__ bias,
            float* __restrict__ out)
{
    extern __shared__ char sm[];
    const uint32_t smb = smem_u32(sm);

    const int tid = threadIdx.x;
    const int wid = tid >> 5;
    const int lid = tid & 31;

    const int p0  = blockIdx.x * TPX;
    const int b   = p0 >> 15;
    const int ho  = (p0 & 32767) >> 8;
    const int wo0 = p0 & 255;

    // GEMM tile: warp (mb = wid&3, nb = wid>>2) owns 32 px x 32 oc
    const int mb = (wid & 3) * 32;
    const int nb = (wid >> 2) * 32;

    wmma::fragment<wmma::accumulator, 16, 16, 16, float> acc[2][2];
    #pragma unroll
    for (int m = 0; m < 2; ++m)
        #pragma unroll
        for (int n = 0; n < 2; ++n) wmma::fill_fragment(acc[m][n], 0.0f);

    // ---- offset prefetch: this thread's meta pixel across all k ----
    const int pxl  = lid & 15;
    const int wo_m = wo0 + wid * 16 + pxl;
    size_t ob = (((size_t)b * (2 * KK)) * HO + ho) * WO + wo_m;  // k = 0
    const size_t ob_step = (size_t)2 * HO * WO;

    float dy_c = __ldg(offset + ob);
    float dx_c = __ldg(offset + ob + (size_t)HO * WO);

    #pragma unroll 1
    for (int k = 0; k < KK; ++k) {
        const int buf = k & 1;
        __half* a_s = (__half*)(sm + buf * A_BYTES);

        // ---- issue offset loads for k+1 FIRST (hide behind gather+GEMM) ----
        float dy_n = 0.0f, dx_n = 0.0f;
        if (k < KK - 1) {
            ob += ob_step;
            dy_n = __ldg(offset + ob);
            dx_n = __ldg(offset + ob + (size_t)HO * WO);
        }

        // ---- stage W(k) -> buf via cp.async (warp: 8 c-rows of 128B) ----
        {
            const uint32_t wb = smb + SM_W + buf * W_BUF;
            const int c   = wid * 8 + (lid >> 2);
            const __half* src = g_wf + k * (C_ * COUT) + c * COUT;
            #pragma unroll
            for (int j = 0; j < 2; ++j) {
                const int seg = (lid & 3) * 2 + j;          // 0..7, 16B each
                cp_async16(wb + c * 144 + seg * 16, src + seg * 8);
            }
            asm volatile("cp.async.commit_group;" ::: "memory");
        }

        // ---- warp-local bilinear meta from prefetched dy/dx ----
        float4 w4m; int4 i4m;
        {
            const int ky = k / 3, kx = k - 3 * ky;
            const float py = (float)(ho - 1 + ky) + dy_c;
            const float px = (float)(wo_m - 1 + kx) + dx_c;
            const float y0f = floorf(py), x0f = floorf(px);
            const float ly = py - y0f,  lx = px - x0f;
            const int y0 = (int)y0f, x0 = (int)x0f;
            const int y1 = y0 + 1,   x1 = x0 + 1;

            const float vy0 = (y0 >= 0 && y0 < H_) ? 1.0f : 0.0f;
            const float vy1 = (y1 >= 0 && y1 < H_) ? 1.0f : 0.0f;
            const float vx0 = (x0 >= 0 && x0 < W_) ? 1.0f : 0.0f;
            const float vx1 = (x1 >= 0 && x1 < W_) ? 1.0f : 0.0f;

            w4m.x = (1.0f - ly) * (1.0f - lx) * vy0 * vx0;
            w4m.y = (1.0f - ly) * lx          * vy0 * vx1;
            w4m.z = ly          * (1.0f - lx) * vy1 * vx0;
            w4m.w = ly          * lx          * vy1 * vx1;

            const int y0c = min(max(y0, 0), H_ - 1);
            const int y1c = min(max(y1, 0), H_ - 1);
            const int x0c = min(max(x0, 0), W_ - 1);
            const int x1c = min(max(x1, 0), W_ - 1);

            const int base = b * HW_;
            i4m.x = (base + y0c * W_ + x0c) * C_;
            i4m.y = (base + y0c * W_ + x1c) * C_;
            i4m.z = (base + y1c * W_ + x0c) * C_;
            i4m.w = (base + y1c * W_ + x1c) * C_;
        }
        dy_c = dy_n;
        dx_c = dx_n;

        // ---- gather warp's 16 px: 4 iters x 4 px, lane = 8 channels ----
        #pragma unroll
        for (int it = 0; it < 4; ++it) {
            const int src = it * 4 + (lid >> 3);            // meta source lane
            const float wx = __shfl_sync(0xffffffffu, w4m.x, src);
            const float wy = __shfl_sync(0xffffffffu, w4m.y, src);
            const float wz = __shfl_sync(0xffffffffu, w4m.z, src);
            const float ww = __shfl_sync(0xffffffffu, w4m.w, src);
            const int   ia = __shfl_sync(0xffffffffu, i4m.x, src);
            const int   ib = __shfl_sync(0xffffffffu, i4m.y, src);
            const int   ic = __shfl_sync(0xffffffffu, i4m.z, src);
            const int   id = __shfl_sync(0xffffffffu, i4m.w, src);

            const __half2 wx2 = __float2half2_rn(wx);
            const __half2 wy2 = __float2half2_rn(wy);
            const __half2 wz2 = __float2half2_rn(wz);
            const __half2 ww2 = __float2half2_rn(ww);

            const int g8 = lid & 7;                         // 16B chunk in row
            const uint4 ua = __ldg((const uint4*)(g_xt + ia) + g8);
            const uint4 ub = __ldg((const uint4*)(g_xt + ib) + g8);
            const uint4 uc = __ldg((const uint4*)(g_xt + ic) + g8);
            const uint4 ud = __ldg((const uint4*)(g_xt + id) + g8);
            const __half2* ha = (const __half2*)&ua;
            const __half2* hb = (const __half2*)&ub;
            const __half2* hc = (const __half2*)&uc;
            const __half2* hd = (const __half2*)&ud;

            uint4 res;
            __half2* rv = (__half2*)&res;
            #pragma unroll
            for (int j = 0; j < 4; ++j) {
                __half2 v = __hmul2(wx2, ha[j]);
                v = __hfma2(wy2, hb[j], v);
                v = __hfma2(wz2, hc[j], v);
                v = __hfma2(ww2, hd[j], v);
                rv[j] = v;
            }

            const int row = wid * 16 + it * 4 + (lid >> 3);
            *(uint4*)(a_s + row * LDA + g8 * 8) = res;
        }

        asm volatile("cp.async.wait_group 0;" ::: "memory");
        __syncthreads();   // the ONE barrier per k (A/W double-buffered)

        // ---- GEMM: 2x2 tile -> 2 fa + 2 fb loads per kt, 4 mma ----
        {
            const __half* w_k  = (const __half*)(sm + SM_W + buf * W_BUF);
            const __half* ar   = a_s + mb * LDA;
            #pragma unroll
            for (int kt = 0; kt < 4; ++kt) {
                wmma::fragment<wmma::matrix_a, 16, 16, 16, __half,
                               wmma::row_major> fa0, fa1;
                wmma::load_matrix_sync(fa0, ar + kt * 16, LDA);
                wmma::load_matrix_sync(fa1, ar + 16 * LDA + kt * 16, LDA);
                wmma::fragment<wmma::matrix_b, 16, 16, 16, __half,
                               wmma::row_major> fb0, fb1;
                wmma::load_matrix_sync(fb0, w_k + kt * 16 * LDB + nb, LDB);
                wmma::load_matrix_sync(fb1, w_k + kt * 16 * LDB + nb + 16, LDB);
                wmma::mma_sync(acc[0][0], fa0, fb0, acc[0][0]);
                wmma::mma_sync(acc[0][1], fa0, fb1, acc[0][1]);
                wmma::mma_sync(acc[1][0], fa1, fb0, acc[1][0]);
                wmma::mma_sync(acc[1][1], fa1, fb1, acc[1][1]);
            }
        }
    }

    // ---- Epilogue: acc -> fp32 smem [128][LDE] -> transposed coalesced STG ----
    __syncthreads();                       // all warps done with A/W smem
    {
        float* smf = (float*)sm;           // reuse A region (34816 <= 36864)
        #pragma unroll
        for (int m = 0; m < 2; ++m)
            #pragma unroll
            for (int n = 0; n < 2; ++n)
                wmma::store_matrix_sync(smf + (mb + m * 16) * LDE + nb + n * 16,
                                        acc[m][n], LDE, wmma::mem_row_major);
    }
    __syncthreads();
    {
        const float* smf = (const float*)sm;
        const int oc_g = tid >> 7;                    // 0/1
        const int pxe  = tid & 127;
        const size_t hw_out = (size_t)ho * WO + wo0 + pxe;
        const float4* b4 = (const float4*)(bias + oc_g * 32);
        #pragma unroll
        for (int o4 = 0; o4 < 8; ++o4) {
            const float4 bb = __ldg(b4 + o4);
            const int oc = oc_g * 32 + o4 * 4;
            out[(size_t)(b * COUT + oc    ) * HW_ + hw_out] = smf[pxe * LDE + oc    ] + bb.x;
            out[(size_t)(b * COUT + oc + 1) * HW_ + hw_out] = smf[pxe * LDE + oc + 1] + bb.y;
            out[(size_t)(b * COUT + oc + 2) * HW_ + hw_out] = smf[pxe * LDE + oc + 2] + bb.z;
            out[(size_t)(b * COUT + oc + 3) * HW_ + hw_out] = smf[pxe * LDE + oc + 3] + bb.w;
        }
    }
}

// ---------------------------------------------------------------------------
extern "C" void kernel_launch(void* const* d_in, const int* in_sizes, int n_in,
                              void* d_out, int out_size)
{
    const float* x      = (const float*)d_in[0];
    const float* offset = (const float*)d_in[1];
    const float* weight = (const float*)d_in[2];
    const float* bias   = (const float*)d_in[3];
    float* out = (float*)d_out;

    cudaFuncSetAttribute(deform_main,
                         cudaFuncAttributeMaxDynamicSharedMemorySize, SM_TOTAL);

    prep<<<4096 + (KK * C_ * COUT + 255) / 256, 256>>>(x, weight);
    deform_main<<<NPIX / TPX, THREADS, SM_TOTAL>>>(offset, bias, out);
}